// round 13
// baseline (speedup 1.0000x reference)
#include <cuda_runtime.h>
#include <cuda_fp16.h>
#include <math.h>
#include <stdint.h>

// ---------------- problem constants ----------------
#define BATCH   2
#define SEQ     2048
#define HIDDEN  4096
#define NH      32
#define NKV     4
#define QKD     192
#define VDIM    128
#define MROWS   (BATCH*SEQ)          // 4096
#define QCOLS   (NH*QKD)             // 6144
#define KCOLS   (NKV*QKD)            // 768
#define VCOLS   (NKV*VDIM)           // 512
#define OCOLS   (NH*VDIM)            // 4096

// ---------------- scratch (device globals: allocation-free) ----------------
__device__ __half g_q  [(size_t)MROWS * QCOLS];
__device__ __half g_k  [(size_t)MROWS * KCOLS];
__device__ __half g_v  [(size_t)MROWS * VCOLS];
__device__ __half g_vt [(size_t)BATCH * NKV * VDIM * SEQ];
__device__ __half g_att[(size_t)MROWS * OCOLS];
__device__ __half g_hs [(size_t)MROWS * HIDDEN];
__device__ __half g_wq [(size_t)QCOLS * HIDDEN];
__device__ __half g_wk [(size_t)KCOLS * HIDDEN];
__device__ __half g_wv [(size_t)VCOLS * HIDDEN];
__device__ __half g_wo [(size_t)HIDDEN * OCOLS];
__device__ float2 g_rope[(size_t)SEQ * 32];

// ---------------- helpers ----------------
__device__ __forceinline__ void mma_f16(float c[4], uint32_t a0, uint32_t a1,
                                        uint32_t a2, uint32_t a3,
                                        uint32_t b0, uint32_t b1)
{
    asm volatile(
        "mma.sync.aligned.m16n8k16.row.col.f32.f16.f16.f32 "
        "{%0,%1,%2,%3}, {%4,%5,%6,%7}, {%8,%9}, {%0,%1,%2,%3};"
        : "+f"(c[0]), "+f"(c[1]), "+f"(c[2]), "+f"(c[3])
        : "r"(a0), "r"(a1), "r"(a2), "r"(a3), "r"(b0), "r"(b1));
}
__device__ __forceinline__ void ldsm4(uint32_t r[4], const __half* p) {
    uint32_t a = (uint32_t)__cvta_generic_to_shared(p);
    asm volatile("ldmatrix.sync.aligned.m8n8.x4.shared.b16 {%0,%1,%2,%3}, [%4];"
                 : "=r"(r[0]), "=r"(r[1]), "=r"(r[2]), "=r"(r[3]) : "r"(a));
}

// ---------------- fp32 -> fp16 conversion (8 elems/thread) ----------------
__global__ void tohalf_kernel(const float4* __restrict__ in, uint4* __restrict__ out,
                              size_t n8)
{
    size_t i = (size_t)blockIdx.x * blockDim.x + threadIdx.x;
    if (i >= n8) return;
    float4 v0 = in[2 * i], v1 = in[2 * i + 1];
    __half2 h0 = __floats2half2_rn(v0.x, v0.y);
    __half2 h1 = __floats2half2_rn(v0.z, v0.w);
    __half2 h2 = __floats2half2_rn(v1.x, v1.y);
    __half2 h3 = __floats2half2_rn(v1.z, v1.w);
    uint4 o;
    o.x = *reinterpret_cast<uint32_t*>(&h0);
    o.y = *reinterpret_cast<uint32_t*>(&h1);
    o.z = *reinterpret_cast<uint32_t*>(&h2);
    o.w = *reinterpret_cast<uint32_t*>(&h3);
    out[i] = o;
}

// ====== fp16 GEMM: CTA 128x128, 4 warps (2x2), warp tile 64x64 ======
// HMMA:LDSM = 32:8 per warp-k16 (ratio 4) -- the GEMM is LDSM-pipe-bound,
// so maximize tensor work per shared-load. 128-thr CTAs at <=170 regs give
// 3 CTAs/SM (12 warps, 3 sync domains). smem 61.4KB*3 = 184KB fits.
#define GSTG 3
#define GSTAGE_H 5120                        // 128*40 halfs per array per stage
#define GEMM_SMEM (GSTG * 2 * GSTAGE_H * 2)  // 61440 B

__global__ __launch_bounds__(128, 3)
void gemm_h(const __half* __restrict__ A, const __half* __restrict__ B,
            void* __restrict__ Cv, int M, int N, int K, int out_half)
{
    extern __shared__ __half smh[];
    __half* As0 = smh;
    __half* Bs0 = smh + GSTG * GSTAGE_H;

    const int tid  = threadIdx.x;
    const int lane = tid & 31;
    const int wid  = tid >> 5;           // 0..3
    const int warpM = (wid >> 1) << 6;   // 0 or 64
    const int warpN = (wid & 1) << 6;    // 0 or 64
    const int gr = lane >> 2;
    const int tg = lane & 3;
    const int l8 = lane & 7;
    const int qd = lane >> 3;

    const int blockRow = blockIdx.y * 128;
    const int blockCol = blockIdx.x * 128;

    float c[4][8][4];
#pragma unroll
    for (int mt = 0; mt < 4; mt++)
#pragma unroll
        for (int nt = 0; nt < 8; nt++)
#pragma unroll
            for (int i = 0; i < 4; i++) c[mt][nt][i] = 0.f;

#define LOAD_STAGE(sp, kb)                                                         \
    do {                                                                           \
        __half* aS = As0 + (sp) * GSTAGE_H;                                        \
        __half* bS = Bs0 + (sp) * GSTAGE_H;                                        \
        _Pragma("unroll")                                                          \
        for (int j_ = 0; j_ < 4; j_++) {                                           \
            int idx_ = tid * 4 + j_;                                               \
            int r_ = idx_ >> 2, ch_ = idx_ & 3;                                    \
            unsigned da_ = (unsigned)__cvta_generic_to_shared(aS + r_*40 + ch_*8); \
            unsigned db_ = (unsigned)__cvta_generic_to_shared(bS + r_*40 + ch_*8); \
            asm volatile("cp.async.ca.shared.global [%0], [%1], 16;" ::            \
                "r"(da_), "l"(A + (size_t)(blockRow + r_) * K + (kb) + ch_*8));    \
            asm volatile("cp.async.ca.shared.global [%0], [%1], 16;" ::            \
                "r"(db_), "l"(B + (size_t)(blockCol + r_) * K + (kb) + ch_*8));    \
        }                                                                          \
    } while (0)

    const int NT = K >> 5;
    LOAD_STAGE(0, 0);
    asm volatile("cp.async.commit_group;");
    LOAD_STAGE(1, 32);
    asm volatile("cp.async.commit_group;");

    const int aoff = ((qd & 1) * 8 + l8) * 40 + (qd >> 1) * 8;
    const int boff = ((qd >> 1) * 8 + l8) * 40 + (qd & 1) * 8;

    for (int t = 0; t < NT; t++) {
        asm volatile("cp.async.wait_group 1;");
        __syncthreads();

        int tp = t + 2;
        if (tp < NT) LOAD_STAGE(tp % GSTG, tp << 5);
        asm volatile("cp.async.commit_group;");

        const __half* aS = As0 + (t % GSTG) * GSTAGE_H;
        const __half* bS = Bs0 + (t % GSTG) * GSTAGE_H;

#pragma unroll
        for (int ks = 0; ks < 2; ks++) {
            const int k0 = ks << 4;
            uint32_t af[4][4];
#pragma unroll
            for (int mt = 0; mt < 4; mt++)
                ldsm4(af[mt], aS + (warpM + mt * 16) * 40 + k0 + aoff);
            // process B in two halves to reduce live-register pressure
#pragma unroll
            for (int half = 0; half < 2; half++) {
                uint32_t bf[2][4];
#pragma unroll
                for (int np = 0; np < 2; np++)
                    ldsm4(bf[np], bS + (warpN + (half * 2 + np) * 16) * 40 + k0 + boff);
#pragma unroll
                for (int mt = 0; mt < 4; mt++)
#pragma unroll
                    for (int nl = 0; nl < 4; nl++) {
                        int nt = half * 4 + nl;
                        mma_f16(c[mt][nt], af[mt][0], af[mt][1], af[mt][2], af[mt][3],
                                bf[nl >> 1][(nl & 1) * 2], bf[nl >> 1][(nl & 1) * 2 + 1]);
                    }
            }
        }
    }
#undef LOAD_STAGE

    if (out_half) {
        __half* C = (__half*)Cv;
#pragma unroll
        for (int mt = 0; mt < 4; mt++) {
            int row = blockRow + warpM + mt * 16 + gr;
#pragma unroll
            for (int nt = 0; nt < 8; nt++) {
                int col = blockCol + warpN + nt * 8 + tg * 2;
                *(__half2*)(C + (size_t)row * N + col) =
                    __floats2half2_rn(c[mt][nt][0], c[mt][nt][1]);
                *(__half2*)(C + (size_t)(row + 8) * N + col) =
                    __floats2half2_rn(c[mt][nt][2], c[mt][nt][3]);
            }
        }
    } else {
        float* C = (float*)Cv;
#pragma unroll
        for (int mt = 0; mt < 4; mt++) {
            int row = blockRow + warpM + mt * 16 + gr;
#pragma unroll
            for (int nt = 0; nt < 8; nt++) {
                int col = blockCol + warpN + nt * 8 + tg * 2;
                *(float2*)(C + (size_t)row * N + col) =
                    make_float2(c[mt][nt][0], c[mt][nt][1]);
                *(float2*)(C + (size_t)(row + 8) * N + col) =
                    make_float2(c[mt][nt][2], c[mt][nt][3]);
            }
        }
    }
}

// ---------------- V transpose ----------------
__global__ void vtrans_kernel(const __half* __restrict__ in, __half* __restrict__ out)
{
    __shared__ __half t[32][33];
    int b  = blockIdx.z;
    int c0 = blockIdx.y * 32;
    int s0 = blockIdx.x * 32;
    int x = threadIdx.x, y = threadIdx.y;
#pragma unroll
    for (int i = 0; i < 32; i += 8)
        t[y + i][x] = in[(size_t)(b * SEQ + s0 + y + i) * VCOLS + c0 + x];
    __syncthreads();
#pragma unroll
    for (int i = 0; i < 32; i += 8) {
        int c = c0 + y + i;
        out[((size_t)(b * NKV + (c >> 7)) * VDIM + (c & 127)) * SEQ + s0 + x] = t[x][y + i];
    }
}

// ---------------- RoPE table + apply ----------------
__global__ void rope_table_kernel()
{
    int i = blockIdx.x * blockDim.x + threadIdx.x;
    int d = i & 31, s = i >> 5;
    float inv = exp2f(-(float)d * (22.253496664211536f / 32.0f));
    float ang = (float)s * inv;
    float sn, cs;
    sincosf(ang, &sn, &cs);
    g_rope[i] = make_float2(cs, sn);
}

__global__ void rope_apply_kernel(__half* __restrict__ x, int nheads, int total)
{
    int idx = blockIdx.x * blockDim.x + threadIdx.x;
    if (idx >= total) return;
    int h   = idx % nheads;
    int row = idx / nheads;
    int s   = row & (SEQ - 1);

    uint4* p4 = (uint4*)(x + (size_t)row * nheads * QKD + h * QKD);
    const float2* tab = g_rope + s * 32;

    uint4 buf[8];
#pragma unroll
    for (int j = 0; j < 8; j++) buf[j] = p4[j];
    __half2* hp = (__half2*)buf;
#pragma unroll
    for (int j = 0; j < 16; j++) {
        float2 a = __half22float2(hp[j]);
        float2 b = __half22float2(hp[j + 16]);
        float2 t0 = tab[2 * j], t1 = tab[2 * j + 1];
        hp[j]      = __floats2half2_rn(a.x * t0.x - b.x * t0.y,
                                       a.y * t1.x - b.y * t1.y);
        hp[j + 16] = __floats2half2_rn(b.x * t0.x + a.x * t0.y,
                                       b.y * t1.x + a.y * t1.y);
    }
#pragma unroll
    for (int j = 0; j < 8; j++) p4[j] = buf[j];
}

// ---------------- Flash attention (R7, unchanged) ----------------
#define HQS 200
#define HPS 72
#define HVS 72
#define FSS 68
#define FLASH_SMEM ((64*HQS + 64*HQS + 128*HVS + 64*HPS) * 2 + (64*FSS + 64 + 64) * 4)

__global__ __launch_bounds__(256)
void flash3_kernel(const __half* __restrict__ Q, const __half* __restrict__ K,
                   const __half* __restrict__ Vt, __half* __restrict__ O)
{
    extern __shared__ char smraw[];
    __half* Qs  = (__half*)smraw;
    __half* Ks  = Qs + 64 * HQS;
    __half* Vs  = Ks + 64 * HQS;
    __half* Ps  = Vs + 128 * HVS;
    float*  Ss  = (float*)(Ps + 64 * HPS);
    float*  scorr = Ss + 64 * FSS;
    float*  slinv = scorr + 64;

    const int qt = blockIdx.x;
    const int h  = blockIdx.y;
    const int b  = blockIdx.z;
    const int kh = h >> 3;

    const int tid  = threadIdx.x;
    const int wid  = tid >> 5;
    const int lane = tid & 31;
    const int gr   = lane >> 2;
    const int tg   = lane & 3;
    const int l8   = lane & 7;
    const int qd   = lane >> 3;
    const int rs   = wid & 3;
    const int ch   = wid >> 2;

    const int r    = tid >> 2;
    const int quad = tid & 3;

    const size_t qbase = ((size_t)(b * SEQ + qt * 64)) * QCOLS + (size_t)h * QKD;
    for (int i = tid; i < 64 * 24; i += 256) {
        int row = i / 24, c8 = i % 24;
        *(uint4*)(Qs + row * HQS + c8 * 8) =
            *(const uint4*)(Q + qbase + (size_t)row * QCOLS + c8 * 8);
    }

    float m = -INFINITY, l = 0.f;
    float acc[8][4];
#pragma unroll
    for (int nt = 0; nt < 8; nt++)
#pragma unroll
        for (int i = 0; i < 4; i++) acc[nt][i] = 0.f;

    const int   qglob = qt * 64 + r;
    const float scale = 0.07216878364870323f;
    const int   nkt   = qt + 1;

    const __half* Qld = Qs + (16 * rs + (qd & 1) * 8 + l8) * HQS + (qd >> 1) * 8;
    const __half* Kld = Ks + (32 * ch + (qd >> 1) * 8 + l8) * HQS + (qd & 1) * 8;
    const __half* Pld = Ps + (16 * rs + (qd & 1) * 8 + l8) * HPS + (qd >> 1) * 8;
    const __half* Vld = Vs + (64 * ch + (qd >> 1) * 8 + l8) * HVS + (qd & 1) * 8;

    const size_t vtbase = ((size_t)(b * NKV + kh) * VDIM) * SEQ;

    for (int kt = 0; kt < nkt; kt++) {
        __syncthreads();

        const size_t kbase = ((size_t)(b * SEQ + kt * 64)) * KCOLS + (size_t)kh * QKD;
        for (int i = tid; i < 64 * 24; i += 256) {
            int row = i / 24, c8 = i % 24;
            *(uint4*)(Ks + row * HQS + c8 * 8) =
                *(const uint4*)(K + kbase + (size_t)row * KCOLS + c8 * 8);
        }
        for (int i = tid; i < 128 * 8; i += 256) {
            int row = i >> 3, c8 = i & 7;
            *(uint4*)(Vs + row * HVS + c8 * 8) =
                *(const uint4*)(Vt + vtbase + (size_t)row * SEQ + kt * 64 + c8 * 8);
        }
        __syncthreads();

        float cf[4][4];
#pragma unroll
        for (int nt = 0; nt < 4; nt++)
#pragma unroll
            for (int i = 0; i < 4; i++) cf[nt][i] = 0.f;

#pragma unroll 4
        for (int ktile = 0; ktile < 12; ktile++) {
            const int k0 = ktile * 16;
            uint32_t af[4], bf0[4], bf1[4];
            ldsm4(af, Qld + k0);
            ldsm4(bf0, Kld + k0);
            ldsm4(bf1, Kld + 16 * HQS + k0);
            mma_f16(cf[0], af[0], af[1], af[2], af[3], bf0[0], bf0[1]);
            mma_f16(cf[1], af[0], af[1], af[2], af[3], bf0[2], bf0[3]);
            mma_f16(cf[2], af[0], af[1], af[2], af[3], bf1[0], bf1[1]);
            mma_f16(cf[3], af[0], af[1], af[2], af[3], bf1[2], bf1[3]);
        }
        {
            float* s0 = Ss + (16 * rs + gr) * FSS + 32 * ch + 2 * tg;
#pragma unroll
            for (int nt = 0; nt < 4; nt++) {
                *(float2*)(s0 + nt * 8)           = make_float2(cf[nt][0], cf[nt][1]);
                *(float2*)(s0 + nt * 8 + 8 * FSS) = make_float2(cf[nt][2], cf[nt][3]);
            }
        }
        __syncthreads();

        {
            float* Srow = Ss + r * FSS;
            __half* Prow = Ps + r * HPS;
            float s[16];
            float tmax = -INFINITY;
#pragma unroll
            for (int j = 0; j < 16; j++) {
                int cg = kt * 64 + 4 * j + quad;
                float v = Srow[4 * j + quad] * scale;
                s[j] = (cg <= qglob) ? v : -INFINITY;
                tmax = fmaxf(tmax, s[j]);
            }
            tmax = fmaxf(tmax, __shfl_xor_sync(0xffffffffu, tmax, 1));
            tmax = fmaxf(tmax, __shfl_xor_sync(0xffffffffu, tmax, 2));
            float mnew = fmaxf(m, tmax);
            float corr = __expf(m - mnew);

            float psum = 0.f;
#pragma unroll
            for (int j = 0; j < 16; j++) {
                __half ph = __float2half_rn(__expf(s[j] - mnew));
                psum += __half2float(ph);
                Prow[4 * j + quad] = ph;
            }
            psum += __shfl_xor_sync(0xffffffffu, psum, 1);
            psum += __shfl_xor_sync(0xffffffffu, psum, 2);
            l = l * corr + psum;
            m = mnew;
            if (quad == 0) scorr[r] = corr;
        }
        __syncthreads();

        {
            float ca = scorr[16 * rs + gr];
            float cb = scorr[16 * rs + gr + 8];
#pragma unroll
            for (int nt = 0; nt < 8; nt++) {
                acc[nt][0] *= ca; acc[nt][1] *= ca;
                acc[nt][2] *= cb; acc[nt][3] *= cb;
            }
#pragma unroll
            for (int ktile = 0; ktile < 4; ktile++) {
                const int k0 = ktile * 16;
                uint32_t af[4];
                ldsm4(af, Pld + k0);
#pragma unroll
                for (int np = 0; np < 4; np++) {
                    uint32_t bf[4];
                    ldsm4(bf, Vld + np * 16 * HVS + k0);
                    mma_f16(acc[2 * np],     af[0], af[1], af[2], af[3], bf[0], bf[1]);
                    mma_f16(acc[2 * np + 1], af[0], af[1], af[2], af[3], bf[2], bf[3]);
                }
            }
        }
    }

    if (quad == 0) slinv[r] = 1.0f / l;
    __syncthreads();

    const int row0 = 16 * rs + gr;
    const float inv0 = slinv[row0];
    const float inv1 = slinv[row0 + 8];
    __half* o0 = O + ((size_t)(b * SEQ + qt * 64 + row0)) * OCOLS
                   + h * VDIM + 64 * ch + 2 * tg;
#pragma unroll
    for (int nt = 0; nt < 8; nt++) {
        *(__half2*)(o0 + nt * 8) =
            __floats2half2_rn(acc[nt][0] * inv0, acc[nt][1] * inv0);
        *(__half2*)(o0 + nt * 8 + 8 * OCOLS) =
            __floats2half2_rn(acc[nt][2] * inv1, acc[nt][3] * inv1);
    }
}

// ---------------- launch ----------------
extern "C" void kernel_launch(void* const* d_in, const int* in_sizes, int n_in,
                              void* d_out, int out_size)
{
    const float* hs = (const float*)d_in[0];
    const float* wq = (const float*)d_in[3];
    const float* wk = (const float*)d_in[4];
    const float* wv = (const float*)d_in[5];
    const float* wo = (const float*)d_in[6];
    float* out = (float*)d_out;

    __half *qb, *kb, *vb, *vtb, *ab, *hsr, *wqr, *wkr, *wvr, *wor;
    cudaGetSymbolAddress((void**)&qb, g_q);
    cudaGetSymbolAddress((void**)&kb, g_k);
    cudaGetSymbolAddress((void**)&vb, g_v);
    cudaGetSymbolAddress((void**)&vtb, g_vt);
    cudaGetSymbolAddress((void**)&ab, g_att);
    cudaGetSymbolAddress((void**)&hsr, g_hs);
    cudaGetSymbolAddress((void**)&wqr, g_wq);
    cudaGetSymbolAddress((void**)&wkr, g_wk);
    cudaGetSymbolAddress((void**)&wvr, g_wv);
    cudaGetSymbolAddress((void**)&wor, g_wo);

    cudaFuncSetAttribute(flash3_kernel, cudaFuncAttributeMaxDynamicSharedMemorySize, FLASH_SMEM);
    cudaFuncSetAttribute(gemm_h, cudaFuncAttributeMaxDynamicSharedMemorySize, GEMM_SMEM);

    static cudaStream_t s1 = nullptr, s2 = nullptr;
    static cudaEvent_t evFork = nullptr, evK = nullptr, evV = nullptr, evWo = nullptr;
    if (s1 == nullptr) {
        cudaStreamCreateWithFlags(&s1, cudaStreamNonBlocking);
        cudaStreamCreateWithFlags(&s2, cudaStreamNonBlocking);
        cudaEventCreateWithFlags(&evFork, cudaEventDisableTiming);
        cudaEventCreateWithFlags(&evK,    cudaEventDisableTiming);
        cudaEventCreateWithFlags(&evV,    cudaEventDisableTiming);
        cudaEventCreateWithFlags(&evWo,   cudaEventDisableTiming);
    }

    dim3 gblk(128);

    // ---- main: rope table + hs conversion ----
    rope_table_kernel<<<SEQ * 32 / 256, 256>>>();
    {
        size_t n = (size_t)MROWS * HIDDEN / 8;
        tohalf_kernel<<<(unsigned)((n + 255) / 256), 256>>>((const float4*)hs, (uint4*)hsr, n);
    }
    cudaEventRecord(evFork, 0);
    cudaStreamWaitEvent(s1, evFork, 0);
    cudaStreamWaitEvent(s2, evFork, 0);

    // ---- s1: K pipeline, then wo conversion ----
    {
        size_t n = (size_t)KCOLS * HIDDEN / 8;
        tohalf_kernel<<<(unsigned)((n + 255) / 256), 256, 0, s1>>>((const float4*)wk, (uint4*)wkr, n);
        gemm_h<<<dim3(KCOLS / 128, MROWS / 128), gblk, GEMM_SMEM, s1>>>(hsr, wkr, kb, MROWS, KCOLS, HIDDEN, 1);
        rope_apply_kernel<<<(MROWS * NKV + 255) / 256, 256, 0, s1>>>(kb, NKV, MROWS * NKV);
        cudaEventRecord(evK, s1);
        n = (size_t)HIDDEN * OCOLS / 8;
        tohalf_kernel<<<(unsigned)((n + 255) / 256), 256, 0, s1>>>((const float4*)wo, (uint4*)wor, n);
        cudaEventRecord(evWo, s1);
    }

    // ---- s2: V pipeline ----
    {
        size_t n = (size_t)VCOLS * HIDDEN / 8;
        tohalf_kernel<<<(unsigned)((n + 255) / 256), 256, 0, s2>>>((const float4*)wv, (uint4*)wvr, n);
        gemm_h<<<dim3(VCOLS / 128, MROWS / 128), gblk, GEMM_SMEM, s2>>>(hsr, wvr, vb, MROWS, VCOLS, HIDDEN, 1);
        vtrans_kernel<<<dim3(SEQ / 32, VCOLS / 32, BATCH), dim3(32, 8), 0, s2>>>(vb, vtb);
        cudaEventRecord(evV, s2);
    }

    // ---- main: Q pipeline ----
    {
        size_t n = (size_t)QCOLS * HIDDEN / 8;
        tohalf_kernel<<<(unsigned)((n + 255) / 256), 256>>>((const float4*)wq, (uint4*)wqr, n);
        gemm_h<<<dim3(QCOLS / 128, MROWS / 128), gblk, GEMM_SMEM>>>(hsr, wqr, qb, MROWS, QCOLS, HIDDEN, 1);
        rope_apply_kernel<<<(MROWS * NH + 255) / 256, 256>>>(qb, NH, MROWS * NH);
    }

    // ---- join: attention, then output projection ----
    cudaStreamWaitEvent(0, evK, 0);
    cudaStreamWaitEvent(0, evV, 0);
    flash3_kernel<<<dim3(SEQ / 64, NH, BATCH), 256, FLASH_SMEM>>>(qb, kb, vtb, ab);
    cudaStreamWaitEvent(0, evWo, 0);
    gemm_h<<<dim3(OCOLS / 128, MROWS / 128), gblk, GEMM_SMEM>>>(ab, wor, out, MROWS, OCOLS, HIDDEN, 0);
}

// round 14
// speedup vs baseline: 1.3207x; 1.3207x over previous
#include <cuda_runtime.h>
#include <cuda_fp16.h>
#include <math.h>
#include <stdint.h>

// ---------------- problem constants ----------------
#define BATCH   2
#define SEQ     2048
#define HIDDEN  4096
#define NH      32
#define NKV     4
#define QKD     192
#define VDIM    128
#define MROWS   (BATCH*SEQ)          // 4096
#define QCOLS   (NH*QKD)             // 6144
#define KCOLS   (NKV*QKD)            // 768
#define VCOLS   (NKV*VDIM)           // 512
#define OCOLS   (NH*VDIM)            // 4096

// ---------------- scratch (device globals: allocation-free) ----------------
__device__ __half g_q  [(size_t)MROWS * QCOLS];
__device__ __half g_k  [(size_t)MROWS * KCOLS];
__device__ __half g_v  [(size_t)MROWS * VCOLS];
__device__ __half g_vt [(size_t)BATCH * NKV * VDIM * SEQ];
__device__ __half g_att[(size_t)MROWS * OCOLS];
__device__ __half g_hs [(size_t)MROWS * HIDDEN];
__device__ __half g_wq [(size_t)QCOLS * HIDDEN];
__device__ __half g_wk [(size_t)KCOLS * HIDDEN];
__device__ __half g_wv [(size_t)VCOLS * HIDDEN];
__device__ __half g_wo [(size_t)HIDDEN * OCOLS];
__device__ float2 g_rope[(size_t)SEQ * 32];

// ---------------- helpers ----------------
__device__ __forceinline__ void mma_f16(float c[4], uint32_t a0, uint32_t a1,
                                        uint32_t a2, uint32_t a3,
                                        uint32_t b0, uint32_t b1)
{
    asm volatile(
        "mma.sync.aligned.m16n8k16.row.col.f32.f16.f16.f32 "
        "{%0,%1,%2,%3}, {%4,%5,%6,%7}, {%8,%9}, {%0,%1,%2,%3};"
        : "+f"(c[0]), "+f"(c[1]), "+f"(c[2]), "+f"(c[3])
        : "r"(a0), "r"(a1), "r"(a2), "r"(a3), "r"(b0), "r"(b1));
}
__device__ __forceinline__ void ldsm4(uint32_t r[4], const __half* p) {
    uint32_t a = (uint32_t)__cvta_generic_to_shared(p);
    asm volatile("ldmatrix.sync.aligned.m8n8.x4.shared.b16 {%0,%1,%2,%3}, [%4];"
                 : "=r"(r[0]), "=r"(r[1]), "=r"(r[2]), "=r"(r[3]) : "r"(a));
}

// ---------------- fp32 -> fp16 conversion (8 elems/thread) ----------------
__global__ void tohalf_kernel(const float4* __restrict__ in, uint4* __restrict__ out,
                              size_t n8)
{
    size_t i = (size_t)blockIdx.x * blockDim.x + threadIdx.x;
    if (i >= n8) return;
    float4 v0 = in[2 * i], v1 = in[2 * i + 1];
    __half2 h0 = __floats2half2_rn(v0.x, v0.y);
    __half2 h1 = __floats2half2_rn(v0.z, v0.w);
    __half2 h2 = __floats2half2_rn(v1.x, v1.y);
    __half2 h3 = __floats2half2_rn(v1.z, v1.w);
    uint4 o;
    o.x = *reinterpret_cast<uint32_t*>(&h0);
    o.y = *reinterpret_cast<uint32_t*>(&h1);
    o.z = *reinterpret_cast<uint32_t*>(&h2);
    o.w = *reinterpret_cast<uint32_t*>(&h3);
    out[i] = o;
}

// ============ fp16 GEMM: CTA 128x128, warp 64x32, 3 stages (R9 exact) =====
#define GSTG 3
#define GSTAGE_H 5120
#define GEMM_SMEM (GSTG * 2 * GSTAGE_H * 2)

__global__ __launch_bounds__(256)
void gemm_h(const __half* __restrict__ A, const __half* __restrict__ B,
            void* __restrict__ Cv, int M, int N, int K, int out_half)
{
    extern __shared__ __half smh[];
    __half* As0 = smh;
    __half* Bs0 = smh + GSTG * GSTAGE_H;

    const int tid  = threadIdx.x;
    const int lane = tid & 31;
    const int wid  = tid >> 5;
    const int warpM = (wid >> 2) << 6;
    const int warpN = (wid & 3) << 5;
    const int gr = lane >> 2;
    const int tg = lane & 3;
    const int l8 = lane & 7;
    const int qd = lane >> 3;

    const int blockRow = blockIdx.y * 128;
    const int blockCol = blockIdx.x * 128;

    float c[4][4][4];
#pragma unroll
    for (int mt = 0; mt < 4; mt++)
#pragma unroll
        for (int nt = 0; nt < 4; nt++)
#pragma unroll
            for (int i = 0; i < 4; i++) c[mt][nt][i] = 0.f;

#define LOAD_STAGE(sp, kb)                                                         \
    do {                                                                           \
        __half* aS = As0 + (sp) * GSTAGE_H;                                        \
        __half* bS = Bs0 + (sp) * GSTAGE_H;                                        \
        _Pragma("unroll")                                                          \
        for (int j_ = 0; j_ < 2; j_++) {                                           \
            int idx_ = tid * 2 + j_;                                               \
            int r_ = idx_ >> 2, ch_ = idx_ & 3;                                    \
            unsigned da_ = (unsigned)__cvta_generic_to_shared(aS + r_*40 + ch_*8); \
            unsigned db_ = (unsigned)__cvta_generic_to_shared(bS + r_*40 + ch_*8); \
            asm volatile("cp.async.ca.shared.global [%0], [%1], 16;" ::            \
                "r"(da_), "l"(A + (size_t)(blockRow + r_) * K + (kb) + ch_*8));    \
            asm volatile("cp.async.ca.shared.global [%0], [%1], 16;" ::            \
                "r"(db_), "l"(B + (size_t)(blockCol + r_) * K + (kb) + ch_*8));    \
        }                                                                          \
    } while (0)

    const int NT = K >> 5;
    LOAD_STAGE(0, 0);
    asm volatile("cp.async.commit_group;");
    LOAD_STAGE(1, 32);
    asm volatile("cp.async.commit_group;");

    const int aoff = ((qd & 1) * 8 + l8) * 40 + (qd >> 1) * 8;
    const int boff = ((qd >> 1) * 8 + l8) * 40 + (qd & 1) * 8;

    for (int t = 0; t < NT; t++) {
        asm volatile("cp.async.wait_group 1;");
        __syncthreads();

        int tp = t + 2;
        if (tp < NT) LOAD_STAGE(tp % GSTG, tp << 5);
        asm volatile("cp.async.commit_group;");

        const __half* aS = As0 + (t % GSTG) * GSTAGE_H;
        const __half* bS = Bs0 + (t % GSTG) * GSTAGE_H;

#pragma unroll
        for (int ks = 0; ks < 2; ks++) {
            const int k0 = ks << 4;
            uint32_t af[4][4], bf[2][4];
#pragma unroll
            for (int mt = 0; mt < 4; mt++)
                ldsm4(af[mt], aS + (warpM + mt * 16) * 40 + k0 + aoff);
#pragma unroll
            for (int np = 0; np < 2; np++)
                ldsm4(bf[np], bS + (warpN + np * 16) * 40 + k0 + boff);
#pragma unroll
            for (int mt = 0; mt < 4; mt++)
#pragma unroll
                for (int nt = 0; nt < 4; nt++)
                    mma_f16(c[mt][nt], af[mt][0], af[mt][1], af[mt][2], af[mt][3],
                            bf[nt >> 1][(nt & 1) * 2], bf[nt >> 1][(nt & 1) * 2 + 1]);
        }
    }
#undef LOAD_STAGE

    if (out_half) {
        __half* C = (__half*)Cv;
#pragma unroll
        for (int mt = 0; mt < 4; mt++) {
            int row = blockRow + warpM + mt * 16 + gr;
#pragma unroll
            for (int nt = 0; nt < 4; nt++) {
                int col = blockCol + warpN + nt * 8 + tg * 2;
                *(__half2*)(C + (size_t)row * N + col) =
                    __floats2half2_rn(c[mt][nt][0], c[mt][nt][1]);
                *(__half2*)(C + (size_t)(row + 8) * N + col) =
                    __floats2half2_rn(c[mt][nt][2], c[mt][nt][3]);
            }
        }
    } else {
        float* C = (float*)Cv;
#pragma unroll
        for (int mt = 0; mt < 4; mt++) {
            int row = blockRow + warpM + mt * 16 + gr;
#pragma unroll
            for (int nt = 0; nt < 4; nt++) {
                int col = blockCol + warpN + nt * 8 + tg * 2;
                *(float2*)(C + (size_t)row * N + col) =
                    make_float2(c[mt][nt][0], c[mt][nt][1]);
                *(float2*)(C + (size_t)(row + 8) * N + col) =
                    make_float2(c[mt][nt][2], c[mt][nt][3]);
            }
        }
    }
}

// ---------------- V transpose ----------------
__global__ void vtrans_kernel(const __half* __restrict__ in, __half* __restrict__ out)
{
    __shared__ __half t[32][33];
    int b  = blockIdx.z;
    int c0 = blockIdx.y * 32;
    int s0 = blockIdx.x * 32;
    int x = threadIdx.x, y = threadIdx.y;
#pragma unroll
    for (int i = 0; i < 32; i += 8)
        t[y + i][x] = in[(size_t)(b * SEQ + s0 + y + i) * VCOLS + c0 + x];
    __syncthreads();
#pragma unroll
    for (int i = 0; i < 32; i += 8) {
        int c = c0 + y + i;
        out[((size_t)(b * NKV + (c >> 7)) * VDIM + (c & 127)) * SEQ + s0 + x] = t[x][y + i];
    }
}

// ---------------- RoPE table + apply ----------------
__global__ void rope_table_kernel()
{
    int i = blockIdx.x * blockDim.x + threadIdx.x;
    int d = i & 31, s = i >> 5;
    float inv = exp2f(-(float)d * (22.253496664211536f / 32.0f));
    float ang = (float)s * inv;
    float sn, cs;
    sincosf(ang, &sn, &cs);
    g_rope[i] = make_float2(cs, sn);
}

// x points at the first row of the region; rows within region < SEQ assumed
// (row & (SEQ-1)) gives the sequence position for both batch halves.
__global__ void rope_apply_kernel(__half* __restrict__ x, int nheads, int total)
{
    int idx = blockIdx.x * blockDim.x + threadIdx.x;
    if (idx >= total) return;
    int h   = idx % nheads;
    int row = idx / nheads;
    int s   = row & (SEQ - 1);

    uint4* p4 = (uint4*)(x + (size_t)row * nheads * QKD + h * QKD);
    const float2* tab = g_rope + s * 32;

    uint4 buf[8];
#pragma unroll
    for (int j = 0; j < 8; j++) buf[j] = p4[j];
    __half2* hp = (__half2*)buf;
#pragma unroll
    for (int j = 0; j < 16; j++) {
        float2 a = __half22float2(hp[j]);
        float2 b = __half22float2(hp[j + 16]);
        float2 t0 = tab[2 * j], t1 = tab[2 * j + 1];
        hp[j]      = __floats2half2_rn(a.x * t0.x - b.x * t0.y,
                                       a.y * t1.x - b.y * t1.y);
        hp[j + 16] = __floats2half2_rn(b.x * t0.x + a.x * t0.y,
                                       b.y * t1.x + a.y * t1.y);
    }
#pragma unroll
    for (int j = 0; j < 8; j++) p4[j] = buf[j];
}

// ---------------- Flash attention (R7 body; batch passed as param) -------
#define HQS 200
#define HPS 72
#define HVS 72
#define FSS 68
#define FLASH_SMEM ((64*HQS + 64*HQS + 128*HVS + 64*HPS) * 2 + (64*FSS + 64 + 64) * 4)

__global__ __launch_bounds__(256)
void flash3_kernel(const __half* __restrict__ Q, const __half* __restrict__ K,
                   const __half* __restrict__ Vt, __half* __restrict__ O, int b)
{
    extern __shared__ char smraw[];
    __half* Qs  = (__half*)smraw;
    __half* Ks  = Qs + 64 * HQS;
    __half* Vs  = Ks + 64 * HQS;
    __half* Ps  = Vs + 128 * HVS;
    float*  Ss  = (float*)(Ps + 64 * HPS);
    float*  scorr = Ss + 64 * FSS;
    float*  slinv = scorr + 64;

    const int qt = blockIdx.x;
    const int h  = blockIdx.y;
    const int kh = h >> 3;

    const int tid  = threadIdx.x;
    const int wid  = tid >> 5;
    const int lane = tid & 31;
    const int gr   = lane >> 2;
    const int tg   = lane & 3;
    const int l8   = lane & 7;
    const int qd   = lane >> 3;
    const int rs   = wid & 3;
    const int ch   = wid >> 2;

    const int r    = tid >> 2;
    const int quad = tid & 3;

    const size_t qbase = ((size_t)(b * SEQ + qt * 64)) * QCOLS + (size_t)h * QKD;
    for (int i = tid; i < 64 * 24; i += 256) {
        int row = i / 24, c8 = i % 24;
        *(uint4*)(Qs + row * HQS + c8 * 8) =
            *(const uint4*)(Q + qbase + (size_t)row * QCOLS + c8 * 8);
    }

    float m = -INFINITY, l = 0.f;
    float acc[8][4];
#pragma unroll
    for (int nt = 0; nt < 8; nt++)
#pragma unroll
        for (int i = 0; i < 4; i++) acc[nt][i] = 0.f;

    const int   qglob = qt * 64 + r;
    const float scale = 0.07216878364870323f;
    const int   nkt   = qt + 1;

    const __half* Qld = Qs + (16 * rs + (qd & 1) * 8 + l8) * HQS + (qd >> 1) * 8;
    const __half* Kld = Ks + (32 * ch + (qd >> 1) * 8 + l8) * HQS + (qd & 1) * 8;
    const __half* Pld = Ps + (16 * rs + (qd & 1) * 8 + l8) * HPS + (qd >> 1) * 8;
    const __half* Vld = Vs + (64 * ch + (qd >> 1) * 8 + l8) * HVS + (qd & 1) * 8;

    const size_t vtbase = ((size_t)(b * NKV + kh) * VDIM) * SEQ;

    for (int kt = 0; kt < nkt; kt++) {
        __syncthreads();

        const size_t kbase = ((size_t)(b * SEQ + kt * 64)) * KCOLS + (size_t)kh * QKD;
        for (int i = tid; i < 64 * 24; i += 256) {
            int row = i / 24, c8 = i % 24;
            *(uint4*)(Ks + row * HQS + c8 * 8) =
                *(const uint4*)(K + kbase + (size_t)row * KCOLS + c8 * 8);
        }
        for (int i = tid; i < 128 * 8; i += 256) {
            int row = i >> 3, c8 = i & 7;
            *(uint4*)(Vs + row * HVS + c8 * 8) =
                *(const uint4*)(Vt + vtbase + (size_t)row * SEQ + kt * 64 + c8 * 8);
        }
        __syncthreads();

        float cf[4][4];
#pragma unroll
        for (int nt = 0; nt < 4; nt++)
#pragma unroll
            for (int i = 0; i < 4; i++) cf[nt][i] = 0.f;

#pragma unroll 4
        for (int ktile = 0; ktile < 12; ktile++) {
            const int k0 = ktile * 16;
            uint32_t af[4], bf0[4], bf1[4];
            ldsm4(af, Qld + k0);
            ldsm4(bf0, Kld + k0);
            ldsm4(bf1, Kld + 16 * HQS + k0);
            mma_f16(cf[0], af[0], af[1], af[2], af[3], bf0[0], bf0[1]);
            mma_f16(cf[1], af[0], af[1], af[2], af[3], bf0[2], bf0[3]);
            mma_f16(cf[2], af[0], af[1], af[2], af[3], bf1[0], bf1[1]);
            mma_f16(cf[3], af[0], af[1], af[2], af[3], bf1[2], bf1[3]);
        }
        {
            float* s0 = Ss + (16 * rs + gr) * FSS + 32 * ch + 2 * tg;
#pragma unroll
            for (int nt = 0; nt < 4; nt++) {
                *(float2*)(s0 + nt * 8)           = make_float2(cf[nt][0], cf[nt][1]);
                *(float2*)(s0 + nt * 8 + 8 * FSS) = make_float2(cf[nt][2], cf[nt][3]);
            }
        }
        __syncthreads();

        {
            float* Srow = Ss + r * FSS;
            __half* Prow = Ps + r * HPS;
            float s[16];
            float tmax = -INFINITY;
#pragma unroll
            for (int j = 0; j < 16; j++) {
                int cg = kt * 64 + 4 * j + quad;
                float v = Srow[4 * j + quad] * scale;
                s[j] = (cg <= qglob) ? v : -INFINITY;
                tmax = fmaxf(tmax, s[j]);
            }
            tmax = fmaxf(tmax, __shfl_xor_sync(0xffffffffu, tmax, 1));
            tmax = fmaxf(tmax, __shfl_xor_sync(0xffffffffu, tmax, 2));
            float mnew = fmaxf(m, tmax);
            float corr = __expf(m - mnew);

            float psum = 0.f;
#pragma unroll
            for (int j = 0; j < 16; j++) {
                __half ph = __float2half_rn(__expf(s[j] - mnew));
                psum += __half2float(ph);
                Prow[4 * j + quad] = ph;
            }
            psum += __shfl_xor_sync(0xffffffffu, psum, 1);
            psum += __shfl_xor_sync(0xffffffffu, psum, 2);
            l = l * corr + psum;
            m = mnew;
            if (quad == 0) scorr[r] = corr;
        }
        __syncthreads();

        {
            float ca = scorr[16 * rs + gr];
            float cb = scorr[16 * rs + gr + 8];
#pragma unroll
            for (int nt = 0; nt < 8; nt++) {
                acc[nt][0] *= ca; acc[nt][1] *= ca;
                acc[nt][2] *= cb; acc[nt][3] *= cb;
            }
#pragma unroll
            for (int ktile = 0; ktile < 4; ktile++) {
                const int k0 = ktile * 16;
                uint32_t af[4];
                ldsm4(af, Pld + k0);
#pragma unroll
                for (int np = 0; np < 4; np++) {
                    uint32_t bf[4];
                    ldsm4(bf, Vld + np * 16 * HVS + k0);
                    mma_f16(acc[2 * np],     af[0], af[1], af[2], af[3], bf[0], bf[1]);
                    mma_f16(acc[2 * np + 1], af[0], af[1], af[2], af[3], bf[2], bf[3]);
                }
            }
        }
    }

    if (quad == 0) slinv[r] = 1.0f / l;
    __syncthreads();

    const int row0 = 16 * rs + gr;
    const float inv0 = slinv[row0];
    const float inv1 = slinv[row0 + 8];
    __half* o0 = O + ((size_t)(b * SEQ + qt * 64 + row0)) * OCOLS
                   + h * VDIM + 64 * ch + 2 * tg;
#pragma unroll
    for (int nt = 0; nt < 8; nt++) {
        *(__half2*)(o0 + nt * 8) =
            __floats2half2_rn(acc[nt][0] * inv0, acc[nt][1] * inv0);
        *(__half2*)(o0 + nt * 8 + 8 * OCOLS) =
            __floats2half2_rn(acc[nt][2] * inv1, acc[nt][3] * inv1);
    }
}

// ---------------- launch: batch-split pipeline ----------------
extern "C" void kernel_launch(void* const* d_in, const int* in_sizes, int n_in,
                              void* d_out, int out_size)
{
    const float* hs = (const float*)d_in[0];
    const float* wq = (const float*)d_in[3];
    const float* wk = (const float*)d_in[4];
    const float* wv = (const float*)d_in[5];
    const float* wo = (const float*)d_in[6];
    float* out = (float*)d_out;

    __half *qb, *kb, *vb, *vtb, *ab, *hsr, *wqr, *wkr, *wvr, *wor;
    cudaGetSymbolAddress((void**)&qb, g_q);
    cudaGetSymbolAddress((void**)&kb, g_k);
    cudaGetSymbolAddress((void**)&vb, g_v);
    cudaGetSymbolAddress((void**)&vtb, g_vt);
    cudaGetSymbolAddress((void**)&ab, g_att);
    cudaGetSymbolAddress((void**)&hsr, g_hs);
    cudaGetSymbolAddress((void**)&wqr, g_wq);
    cudaGetSymbolAddress((void**)&wkr, g_wk);
    cudaGetSymbolAddress((void**)&wvr, g_wv);
    cudaGetSymbolAddress((void**)&wor, g_wo);

    cudaFuncSetAttribute(flash3_kernel, cudaFuncAttributeMaxDynamicSharedMemorySize, FLASH_SMEM);
    cudaFuncSetAttribute(gemm_h, cudaFuncAttributeMaxDynamicSharedMemorySize, GEMM_SMEM);

    static cudaStream_t s1 = nullptr, s2 = nullptr, s3 = nullptr;
    static cudaEvent_t evFork = nullptr, evK = nullptr, evV = nullptr,
                       evWo = nullptr, evWq = nullptr, evF1 = nullptr;
    if (s1 == nullptr) {
        cudaStreamCreateWithFlags(&s1, cudaStreamNonBlocking);
        cudaStreamCreateWithFlags(&s2, cudaStreamNonBlocking);
        cudaStreamCreateWithFlags(&s3, cudaStreamNonBlocking);
        cudaEventCreateWithFlags(&evFork, cudaEventDisableTiming);
        cudaEventCreateWithFlags(&evK,    cudaEventDisableTiming);
        cudaEventCreateWithFlags(&evV,    cudaEventDisableTiming);
        cudaEventCreateWithFlags(&evWo,   cudaEventDisableTiming);
        cudaEventCreateWithFlags(&evWq,   cudaEventDisableTiming);
        cudaEventCreateWithFlags(&evF1,   cudaEventDisableTiming);
    }

    dim3 blk(256);
    const size_t halfQ  = (size_t)SEQ * QCOLS;   // q rows per batch
    const size_t halfO  = (size_t)SEQ * OCOLS;   // att rows per batch
    const size_t halfHs = (size_t)SEQ * HIDDEN;

    // ---- main: rope table + hs conversion (full) ----
    rope_table_kernel<<<SEQ * 32 / 256, 256>>>();
    {
        size_t n = (size_t)MROWS * HIDDEN / 8;
        tohalf_kernel<<<(unsigned)((n + 255) / 256), 256>>>((const float4*)hs, (uint4*)hsr, n);
    }
    cudaEventRecord(evFork, 0);
    cudaStreamWaitEvent(s1, evFork, 0);
    cudaStreamWaitEvent(s2, evFork, 0);

    // ---- s1: K pipeline (full), then wo conversion ----
    {
        size_t n = (size_t)KCOLS * HIDDEN / 8;
        tohalf_kernel<<<(unsigned)((n + 255) / 256), 256, 0, s1>>>((const float4*)wk, (uint4*)wkr, n);
        gemm_h<<<dim3(KCOLS / 128, MROWS / 128), blk, GEMM_SMEM, s1>>>(hsr, wkr, kb, MROWS, KCOLS, HIDDEN, 1);
        rope_apply_kernel<<<(MROWS * NKV + 255) / 256, 256, 0, s1>>>(kb, NKV, MROWS * NKV);
        cudaEventRecord(evK, s1);
        n = (size_t)HIDDEN * OCOLS / 8;
        tohalf_kernel<<<(unsigned)((n + 255) / 256), 256, 0, s1>>>((const float4*)wo, (uint4*)wor, n);
        cudaEventRecord(evWo, s1);
    }

    // ---- s2: V pipeline (full) ----
    {
        size_t n = (size_t)VCOLS * HIDDEN / 8;
        tohalf_kernel<<<(unsigned)((n + 255) / 256), 256, 0, s2>>>((const float4*)wv, (uint4*)wvr, n);
        gemm_h<<<dim3(VCOLS / 128, MROWS / 128), blk, GEMM_SMEM, s2>>>(hsr, wvr, vb, MROWS, VCOLS, HIDDEN, 1);
        vtrans_kernel<<<dim3(SEQ / 32, VCOLS / 32, BATCH), dim3(32, 8), 0, s2>>>(vb, vtb);
        cudaEventRecord(evV, s2);
    }

    // ---- main: wq conversion, then batch-0 Q pipeline ----
    {
        size_t n = (size_t)QCOLS * HIDDEN / 8;
        tohalf_kernel<<<(unsigned)((n + 255) / 256), 256>>>((const float4*)wq, (uint4*)wqr, n);
    }
    cudaEventRecord(evWq, 0);
    cudaStreamWaitEvent(s3, evWq, 0);

    // main: Q(b0) -> rope(b0) -> flash(b0)
    gemm_h<<<dim3(QCOLS / 128, SEQ / 128), blk, GEMM_SMEM>>>(hsr, wqr, qb, SEQ, QCOLS, HIDDEN, 1);
    rope_apply_kernel<<<(SEQ * NH + 255) / 256, 256>>>(qb, NH, SEQ * NH);
    cudaStreamWaitEvent(0, evK, 0);
    cudaStreamWaitEvent(0, evV, 0);
    flash3_kernel<<<dim3(SEQ / 64, NH, 1), 256, FLASH_SMEM>>>(qb, kb, vtb, ab, 0);

    // s3: Q(b1) -> rope(b1) -> flash(b1)
    gemm_h<<<dim3(QCOLS / 128, SEQ / 128), blk, GEMM_SMEM, s3>>>(hsr + halfHs, wqr,
                                                                 qb + halfQ, SEQ, QCOLS, HIDDEN, 1);
    rope_apply_kernel<<<(SEQ * NH + 255) / 256, 256, 0, s3>>>(qb + halfQ, NH, SEQ * NH);
    cudaStreamWaitEvent(s3, evK, 0);
    cudaStreamWaitEvent(s3, evV, 0);
    flash3_kernel<<<dim3(SEQ / 64, NH, 1), 256, FLASH_SMEM, s3>>>(qb, kb, vtb, ab, 1);
    cudaEventRecord(evF1, s3);

    // main: wo(b0) (overlaps flash(b1)), then wo(b1)
    cudaStreamWaitEvent(0, evWo, 0);
    gemm_h<<<dim3(OCOLS / 128, SEQ / 128), blk, GEMM_SMEM>>>(ab, wor, out, SEQ, OCOLS, HIDDEN, 0);
    cudaStreamWaitEvent(0, evF1, 0);
    gemm_h<<<dim3(OCOLS / 128, SEQ / 128), blk, GEMM_SMEM>>>(ab + halfO, wor,
                                                             out + halfHs, SEQ, OCOLS, HIDDEN, 0);
}